// round 6
// baseline (speedup 1.0000x reference)
#include <cuda_runtime.h>

// DilateAttention: B=8, C=384 (12 heads x 32), H=W=56, kernel 3x3, dilation 2, pad 2.
// q,k,v: [B, C, H, W] f32. out: [B, H, W, C] f32.
//
// R6: smem-tiled with zero-ALU indexing. Block = (8-row strip, head, b), 448
// threads = 1 px each. k/v processed in 4 channel-chunks of 8: cooperative
// coalesced load of a zero-padded [8][12][64] tile (slot index == loader index,
// r=i>>6, xl=i&63), then 9-neighbor accumulation reading smem at compile-time
// constant offsets. OOB slots hold 0 -> logit 0, matching unfold zero-padding.
// Output staged per chunk and written as coalesced float4 (store of chunk c
// overlapped with tile load of chunk c+1).

#define HD     32
#define HEADS  12
#define WD     56
#define HT     56
#define BD     8
#define HW     (WD * HT)
#define CTOT   384
#define NTHR   448
#define TY     8
#define TROWS  12
#define TCOLS  64
#define TSLOTS (TROWS * TCOLS)   // 768
#define CC     8
#define NCH    4

__global__ __launch_bounds__(NTHR, 3)
void dilate_attn_kernel(const float* __restrict__ q,
                        const float* __restrict__ k,
                        const float* __restrict__ v,
                        float* __restrict__ out)
{
    __shared__ float tile[CC * TSLOTS];                  // 24 KB
    __shared__ __align__(16) float stageS[NTHR * CC];    // 14 KB
    __shared__ int sOb[NTHR];

    const int tid  = threadIdx.x;
    const int y0   = blockIdx.x * TY;
    const int head = blockIdx.y;
    const int b    = blockIdx.z;

    const int ly = tid / WD;
    const int x  = tid - ly * WD;
    const int gy = y0 + ly;

    const int base = (b * CTOT + head * HD) * HW;
    const int pix  = gy * WD + x;

    sOb[tid] = ((b * HT + gy) * WD + x) * CTOT + head * HD;

    // ---- loader slots (computed once, reused for all 8 tile loads) ----
    const int i0 = tid;                 // always < TSLOTS
    const int i1 = tid + NTHR;          // may exceed TSLOTS
    const bool has1 = (i1 < TSLOTS);
    const int r0 = i0 >> 6, xl0 = i0 & 63;
    const int r1 = i1 >> 6, xl1 = i1 & 63;
    const int gy0 = y0 - 2 + r0, gx0 = xl0 - 2;
    const int gy1 = y0 - 2 + r1, gx1 = xl1 - 2;
    const bool v0 = ((unsigned)gy0 < (unsigned)HT) && ((unsigned)gx0 < (unsigned)WD);
    const bool v1 = has1 && ((unsigned)gy1 < (unsigned)HT) && ((unsigned)gx1 < (unsigned)WD);
    const int goff0 = gy0 * WD + gx0;
    const int goff1 = gy1 * WD + gx1;

    const float* tb = &tile[ly * TCOLS + x];   // compute-phase base

    float attn[9];
#pragma unroll
    for (int p = 0; p < 9; p++) attn[p] = 0.0f;

    // ================= K phase =================
    {
        const float* qp = q + base + pix;
#pragma unroll
        for (int ch = 0; ch < NCH; ch++) {
            const float* pc = k + base + ch * CC * HW;
            __syncthreads();
#pragma unroll
            for (int c = 0; c < CC; c++) {
                float a = v0 ? pc[goff0 + c * HW] : 0.0f;
                tile[c * TSLOTS + i0] = a;
                if (has1) {
                    float bb = v1 ? pc[goff1 + c * HW] : 0.0f;
                    tile[c * TSLOTS + i1] = bb;
                }
            }
            __syncthreads();

            float qv[CC];
#pragma unroll
            for (int c = 0; c < CC; c++) qv[c] = qp[(ch * CC + c) * HW];

#pragma unroll
            for (int py = 0; py < 3; py++) {
#pragma unroll
                for (int px = 0; px < 3; px++) {
                    float s = attn[py * 3 + px];
#pragma unroll
                    for (int c = 0; c < CC; c++)
                        s = fmaf(qv[c], tb[c * TSLOTS + py * 2 * TCOLS + px * 2], s);
                    attn[py * 3 + px] = s;
                }
            }
        }
    }

    // ================= softmax (normalization folded into weights) =================
    {
        const float scale = 0.17677669529663687f;  // 32^-0.5
        float m = -1e30f;
#pragma unroll
        for (int p = 0; p < 9; p++) { attn[p] *= scale; m = fmaxf(m, attn[p]); }
        float d = 0.0f;
#pragma unroll
        for (int p = 0; p < 9; p++) { attn[p] = __expf(attn[p] - m); d += attn[p]; }
        float inv = 1.0f / d;
#pragma unroll
        for (int p = 0; p < 9; p++) attn[p] *= inv;
    }

    // ================= V phase (store of chunk c overlapped with load of c+1) ====
#pragma unroll
    for (int ch = 0; ch < NCH; ch++) {
        const float* pc = v + base + ch * CC * HW;
        __syncthreads();
        // tile load of chunk ch
#pragma unroll
        for (int c = 0; c < CC; c++) {
            float a = v0 ? pc[goff0 + c * HW] : 0.0f;
            tile[c * TSLOTS + i0] = a;
            if (has1) {
                float bb = v1 ? pc[goff1 + c * HW] : 0.0f;
                tile[c * TSLOTS + i1] = bb;
            }
        }
        // store-out of chunk ch-1 (reads stageS written before the sync above)
        if (ch > 0) {
            const int chp = ch - 1;
#pragma unroll
            for (int j = 0; j < 2; j++) {
                int idx = tid + NTHR * j;          // 0..895
                int px  = idx >> 1;
                int ci  = (idx & 1) << 2;
                float4 val = *(const float4*)&stageS[px * CC + ci];
                *(float4*)(out + sOb[px] + chp * CC + ci) = val;
            }
        }
        __syncthreads();

        float acc[CC];
#pragma unroll
        for (int c = 0; c < CC; c++) acc[c] = 0.0f;
#pragma unroll
        for (int py = 0; py < 3; py++) {
#pragma unroll
            for (int px = 0; px < 3; px++) {
                const float w = attn[py * 3 + px];
#pragma unroll
                for (int c = 0; c < CC; c++)
                    acc[c] = fmaf(w, tb[c * TSLOTS + py * 2 * TCOLS + px * 2], acc[c]);
            }
        }
        *(float4*)&stageS[tid * CC]     = make_float4(acc[0], acc[1], acc[2], acc[3]);
        *(float4*)&stageS[tid * CC + 4] = make_float4(acc[4], acc[5], acc[6], acc[7]);
    }

    __syncthreads();
    // final store-out (chunk 3)
#pragma unroll
    for (int j = 0; j < 2; j++) {
        int idx = tid + NTHR * j;
        int px  = idx >> 1;
        int ci  = (idx & 1) << 2;
        float4 val = *(const float4*)&stageS[px * CC + ci];
        *(float4*)(out + sOb[px] + 3 * CC + ci) = val;
    }
}

extern "C" void kernel_launch(void* const* d_in, const int* in_sizes, int n_in,
                              void* d_out, int out_size)
{
    const float* q = (const float*)d_in[0];
    const float* k = (const float*)d_in[1];
    const float* v = (const float*)d_in[2];
    float* out = (float*)d_out;

    dim3 grid(HT / TY, HEADS, BD);   // 7 x 12 x 8 = 672 blocks
    dilate_attn_kernel<<<grid, NTHR>>>(q, k, v, out);
}

// round 7
// speedup vs baseline: 2.4040x; 2.4040x over previous
#include <cuda_runtime.h>

// DilateAttention: B=8, C=384 (12 heads x 32), H=W=56, kernel 3x3, dilation 2, pad 2.
// q,k,v: [B, C, H, W] f32. out: [B, H, W, C] f32.
//
// R7: R5 skeleton (guarded neighbor skip, channel-chunked) but 2 pixels/thread
// with float2 window loads: for each (channel,row) three aligned LDG.64 at
// x0-2 / x0 / x0+2 serve BOTH pixels' three x-neighbors (.x -> px0, .y -> px1),
// halving LSU-issue count per pixel (the measured bottleneck in R1/R5).
// Invalid windows are skipped entirely -> logit stays 0 (unfold zero-padding).
// No barriers; direct full-sector stores.

#define HD     32
#define HEADS  12
#define WD     56
#define HT     56
#define BD     8
#define HW     (WD * HT)
#define CTOT   384
#define XG     28          // x-pairs per row
#define NTHR   256
#define CC     8
#define NCH    4

__global__ __launch_bounds__(NTHR, 4)
void dilate_attn_kernel(const float* __restrict__ q,
                        const float* __restrict__ k,
                        const float* __restrict__ v,
                        float* __restrict__ out)
{
    const int gid  = blockIdx.x * NTHR + threadIdx.x;
    const int xg   = gid % XG;
    int r1         = gid / XG;
    const int y    = r1 % HT;
    int r2         = r1 / HT;
    const int head = r2 % HEADS;
    const int b    = r2 / HEADS;
    const int x0   = xg * 2;

    const int base = (b * CTOT + head * HD) * HW;
    const int pix  = y * WD + x0;

    const bool cL = (x0 >= 2);
    const bool cR = (x0 <= WD - 4);
    const bool yT = (y >= 2);
    const bool yB = (y <= HT - 3);

    const bool vmask[9] = {
        yT && cL, yT, yT && cR,
        cL,       true, cR,
        yB && cL, yB, yB && cR
    };
    const int voff[9] = {
        -2 * WD - 2, -2 * WD, -2 * WD + 2,
        -2,           0,       2,
         2 * WD - 2,  2 * WD,  2 * WD + 2
    };

    const float* qc = q + base + pix;
    const float* kc = k + base + pix;
    const float* vc = v + base + pix;

    float a0[9], a1[9];
#pragma unroll
    for (int p = 0; p < 9; p++) { a0[p] = 0.0f; a1[p] = 0.0f; }

    // ================= K phase: logits, channel chunks of 8 =================
#pragma unroll
    for (int ch = 0; ch < NCH; ch++) {
        float2 qv[CC];
#pragma unroll
        for (int c = 0; c < CC; c++)
            qv[c] = *(const float2*)(qc + (ch * CC + c) * HW);

#pragma unroll
        for (int p = 0; p < 9; p++) {
            if (vmask[p]) {
                const float* kp = kc + ch * CC * HW + voff[p];
                float s0 = a0[p], s1 = a1[p];
#pragma unroll
                for (int c = 0; c < CC; c++) {
                    float2 kv = *(const float2*)(kp + c * HW);
                    s0 = fmaf(qv[c].x, kv.x, s0);
                    s1 = fmaf(qv[c].y, kv.y, s1);
                }
                a0[p] = s0; a1[p] = s1;
            }
        }
    }

    // ================= softmax (normalization folded into weights) =================
    {
        const float scale = 0.17677669529663687f;  // 32^-0.5
        float m0 = -1e30f, m1 = -1e30f;
#pragma unroll
        for (int p = 0; p < 9; p++) {
            a0[p] *= scale; a1[p] *= scale;
            m0 = fmaxf(m0, a0[p]); m1 = fmaxf(m1, a1[p]);
        }
        float d0 = 0.0f, d1 = 0.0f;
#pragma unroll
        for (int p = 0; p < 9; p++) {
            a0[p] = __expf(a0[p] - m0); d0 += a0[p];
            a1[p] = __expf(a1[p] - m1); d1 += a1[p];
        }
        float i0 = 1.0f / d0, i1 = 1.0f / d1;
#pragma unroll
        for (int p = 0; p < 9; p++) { a0[p] *= i0; a1[p] *= i1; }
    }

    // ================= V phase: weighted sum + direct stores =================
    const int ob = ((b * HT + y) * WD + x0) * CTOT + head * HD;

#pragma unroll
    for (int ch = 0; ch < NCH; ch++) {
        float acc0[CC], acc1[CC];
#pragma unroll
        for (int c = 0; c < CC; c++) { acc0[c] = 0.0f; acc1[c] = 0.0f; }

#pragma unroll
        for (int p = 0; p < 9; p++) {
            if (vmask[p]) {
                const float w0 = a0[p], w1 = a1[p];
                const float* vp = vc + ch * CC * HW + voff[p];
#pragma unroll
                for (int c = 0; c < CC; c++) {
                    float2 vv = *(const float2*)(vp + c * HW);
                    acc0[c] = fmaf(w0, vv.x, acc0[c]);
                    acc1[c] = fmaf(w1, vv.y, acc1[c]);
                }
            }
        }

        float* o0 = out + ob + ch * CC;
        *(float4*)(o0)            = make_float4(acc0[0], acc0[1], acc0[2], acc0[3]);
        *(float4*)(o0 + 4)        = make_float4(acc0[4], acc0[5], acc0[6], acc0[7]);
        *(float4*)(o0 + CTOT)     = make_float4(acc1[0], acc1[1], acc1[2], acc1[3]);
        *(float4*)(o0 + CTOT + 4) = make_float4(acc1[4], acc1[5], acc1[6], acc1[7]);
    }
}

extern "C" void kernel_launch(void* const* d_in, const int* in_sizes, int n_in,
                              void* d_out, int out_size)
{
    const float* q = (const float*)d_in[0];
    const float* k = (const float*)d_in[1];
    const float* v = (const float*)d_in[2];
    float* out = (float*)d_out;

    int total  = BD * HEADS * HT * XG;   // 150528 threads (2 px each)
    int blocks = total / NTHR;           // 588
    dilate_attn_kernel<<<blocks, NTHR>>>(q, k, v, out);
}